// round 4
// baseline (speedup 1.0000x reference)
#include <cuda_runtime.h>

// glb_pos [B,T,J,3], glb_rot [B,T,J,4], glb_vel [B,T-1,J,3], root_rotation [B,T,1,4]
// Output: pos_out [B,T,J,3] then rot_out [B,T,J,4], float32.

#define MAX_B 64
#define MAX_T 1024

__device__ float2 g_traj2[MAX_B * MAX_T];  // fast path: (x,z) trajectory
__device__ float3 g_traj[MAX_B * MAX_T];   // fallback path scratch
__device__ int g_done = 0;                 // producers finished counter
__device__ int g_exit = 0;                 // block exit counter (for reset)

struct Q { float w, x, y, z; };

__device__ __forceinline__ Q qmul(Q a, Q b) {
    Q r;
    r.w = a.w * b.w - a.x * b.x - a.y * b.y - a.z * b.z;
    r.x = a.w * b.x + a.x * b.w + a.y * b.z - a.z * b.y;
    r.y = a.w * b.y - a.x * b.z + a.y * b.w + a.z * b.x;
    r.z = a.w * b.z + a.x * b.y - a.y * b.x + a.z * b.w;
    return r;
}

__device__ __forceinline__ float3 qapply(Q q, float3 p) {
    Q pq; pq.w = 0.f; pq.x = p.x; pq.y = p.y; pq.z = p.z;
    Q t = qmul(q, pq);
    Q c; c.w = q.w; c.x = -q.x; c.y = -q.y; c.z = -q.z;
    Q r = qmul(t, c);
    return make_float3(r.x, r.y, r.z);
}

__device__ __forceinline__ Q load_inv(const float4* __restrict__ root, int idx) {
    float4 v = __ldg(root + idx);                        // (w,x,y,z) real-first
    Q q; q.w = v.x; q.x = -v.y; q.y = -v.z; q.z = -v.w;  // conjugate
    return q;
}

// ===========================================================================
// FAST PATH: ONE kernel. B==64, T==1024, J==32. Grid = 2048 blocks x 256.
//  Stage 1 (blocks 0..63): per-batch trajectory scan -> g_traj2, release flag.
//  Stage 2 (all blocks):   rot share (1024 quats/block), coalesced float4.
//  Stage 3 (all blocks):   wait flag (already set), pos share (1024 elems),
//                          staged through smem for coalesced global IO.
//  Counters self-reset when the last block exits (graph-replay safe).
// ===========================================================================
__global__ void __launch_bounds__(256) fused_one(
    const float4* __restrict__ glb_pos4,
    const float4* __restrict__ glb_rot4,
    const float* __restrict__ glb_vel,
    const float4* __restrict__ root,
    float4* __restrict__ out_pos4,
    float4* __restrict__ out_rot4)
{
    const int T = 1024, J = 32;
    const int tid = threadIdx.x;
    const int blk = blockIdx.x;

    __shared__ float s_buf[3072];          // 12 KB pos staging (1024 elems)
    __shared__ float3 s_ws[8];
    __shared__ float3 s_pos0;

    // ---------------- Stage 1: trajectory scan (blocks 0..63) --------------
    if (blk < 64) {
        const int b = blk;
        const int lane = tid & 31, warp = tid >> 5;
        const float* glb_pos = (const float*)glb_pos4;

        float3 vr[4];
        float3 acc = make_float3(0.f, 0.f, 0.f);
        #pragma unroll
        for (int k = 0; k < 4; ++k) {
            int t = tid * 4 + k;
            Q inv = load_inv(root, b * T + t);
            float3 v = make_float3(0.f, 0.f, 0.f);
            if (t < T - 1) {
                const float* vp = glb_vel + ((b * (T - 1) + t) * J) * 3;  // joint 0
                v = qapply(inv, make_float3(__ldg(vp), __ldg(vp + 1), __ldg(vp + 2)));
            }
            if (t == 0) {
                const float* pp = glb_pos + (long)b * T * J * 3;
                s_pos0 = qapply(inv, make_float3(__ldg(pp), __ldg(pp + 1), __ldg(pp + 2)));
            }
            acc.x += v.x; acc.y += v.y; acc.z += v.z;
            vr[k] = acc;
        }

        float3 s = acc;
        #pragma unroll
        for (int o = 1; o < 32; o <<= 1) {
            float ax = __shfl_up_sync(0xFFFFFFFFu, s.x, o);
            float ay = __shfl_up_sync(0xFFFFFFFFu, s.y, o);
            float az = __shfl_up_sync(0xFFFFFFFFu, s.z, o);
            if (lane >= o) { s.x += ax; s.y += ay; s.z += az; }
        }
        if (lane == 31) s_ws[warp] = s;
        __syncthreads();
        if (warp == 0 && lane < 8) {
            float3 ws = s_ws[lane];
            #pragma unroll
            for (int o = 1; o < 8; o <<= 1) {
                float ax = __shfl_up_sync(0x000000FFu, ws.x, o);
                float ay = __shfl_up_sync(0x000000FFu, ws.y, o);
                float az = __shfl_up_sync(0x000000FFu, ws.z, o);
                if (lane >= o) { ws.x += ax; ws.y += ay; ws.z += az; }
            }
            s_ws[lane] = ws;
        }
        __syncthreads();

        float3 wpre = (warp > 0) ? s_ws[warp - 1] : make_float3(0.f, 0.f, 0.f);
        float3 incl = make_float3(s.x + wpre.x, s.y + wpre.y, s.z + wpre.z);
        float3 excl;
        excl.x = __shfl_up_sync(0xFFFFFFFFu, incl.x, 1);
        excl.y = __shfl_up_sync(0xFFFFFFFFu, incl.y, 1);
        excl.z = __shfl_up_sync(0xFFFFFFFFu, incl.z, 1);
        if (lane == 0) excl = wpre;

        float3 p0 = s_pos0;
        #pragma unroll
        for (int k = 0; k < 4; ++k) {
            float ex = excl.x, ez = excl.z;
            if (k > 0) { ex += vr[k - 1].x; ez += vr[k - 1].z; }
            g_traj2[b * T + tid * 4 + k] = make_float2(p0.x + ex, p0.z + ez);
        }

        __syncthreads();
        __threadfence();
        if (tid == 0) atomicAdd(&g_done, 1);
    }

    // ---------------- Stage 2: rot share (all blocks) ----------------------
    // Block handles quats [blk*1024, blk*1024+1024). Consecutive lanes hit
    // consecutive float4s: fully coalesced.
    {
        const int base = blk * 1024;
        #pragma unroll
        for (int k = 0; k < 4; ++k) {
            int idx = base + k * 256 + tid;
            Q inv = load_inv(root, idx >> 5);         // (b*T+t), warp-uniform
            float4 r4 = __ldg(glb_rot4 + idx);
            Q r; r.w = r4.x; r.x = r4.y; r.y = r4.z; r.z = r4.w;
            Q m = qmul(inv, r);
            if (m.w < 0.f) { m.w = -m.w; m.x = -m.x; m.y = -m.y; m.z = -m.z; }
            out_rot4[idx] = make_float4(m.w, m.x, m.y, m.z);
        }
    }

    // ---------------- wait for trajectory (normally already done) ----------
    if (tid == 0) {
        while (atomicAdd(&g_done, 0) < 64) __nanosleep(64);
    }
    __syncthreads();
    __threadfence();   // acquire g_traj2

    // ---------------- Stage 3: pos share via smem staging ------------------
    {
        const int e0 = blk * 1024;                     // first element
        const int f4base = blk * 768;                  // first float4 of slice
        // coalesced global -> smem (768 float4 per block)
        #pragma unroll
        for (int k = 0; k < 3; ++k) {
            float4 v = __ldg(glb_pos4 + f4base + k * 256 + tid);
            ((float4*)s_buf)[k * 256 + tid] = v;
        }
        __syncthreads();

        // per-thread: 4 elements = 12 floats, all from own smem region
        const int e = e0 + tid * 4;
        const int bt = e >> 5;                         // same for all 4 elems
        Q inv = load_inv(root, bt);
        float2 tr = g_traj2[bt];

        float f[12];
        #pragma unroll
        for (int k = 0; k < 12; ++k) f[k] = s_buf[tid * 12 + k];

        float o[12];
        #pragma unroll
        for (int m = 0; m < 4; ++m) {
            float3 r = qapply(inv, make_float3(f[3 * m], f[3 * m + 1], f[3 * m + 2]));
            o[3 * m]     = r.x + tr.x;
            o[3 * m + 1] = r.y;                        // xz mask: y untouched
            o[3 * m + 2] = r.z + tr.y;
        }
        __syncthreads();
        #pragma unroll
        for (int k = 0; k < 12; ++k) s_buf[tid * 12 + k] = o[k];
        __syncthreads();

        // coalesced smem -> global
        #pragma unroll
        for (int k = 0; k < 3; ++k)
            out_pos4[f4base + k * 256 + tid] = ((float4*)s_buf)[k * 256 + tid];
    }

    // ---------------- self-reset of flags (last block out) ------------------
    __syncthreads();
    if (tid == 0) {
        int prev = atomicAdd(&g_exit, 1);
        if (prev == (int)gridDim.x - 1) { g_done = 0; g_exit = 0; }
    }
}

// ===========================================================================
// Fallback (generic dims): R1's proven two-kernel path.
// ===========================================================================
__global__ void __launch_bounds__(1024) traj_kernel(
    const float* __restrict__ glb_pos,
    const float* __restrict__ glb_vel,
    const float4* __restrict__ root,
    int T, int J)
{
    const int b = blockIdx.x;
    const int t = threadIdx.x;
    const int lane = t & 31, warp = t >> 5;
    __shared__ float3 s_wsum[32];
    __shared__ float3 s_pos0;
    if (t >= T) return;

    Q inv = load_inv(root, b * T + t);
    float3 v = make_float3(0.f, 0.f, 0.f);
    if (t < T - 1) {
        const float* vp = glb_vel + ((long)(b * (T - 1) + t) * J) * 3;
        v = qapply(inv, make_float3(__ldg(vp), __ldg(vp + 1), __ldg(vp + 2)));
    }
    if (t == 0) {
        const float* pp = glb_pos + (long)b * T * J * 3;
        s_pos0 = qapply(inv, make_float3(__ldg(pp), __ldg(pp + 1), __ldg(pp + 2)));
    }
    float3 s = v;
    #pragma unroll
    for (int o = 1; o < 32; o <<= 1) {
        float ax = __shfl_up_sync(0xFFFFFFFFu, s.x, o);
        float ay = __shfl_up_sync(0xFFFFFFFFu, s.y, o);
        float az = __shfl_up_sync(0xFFFFFFFFu, s.z, o);
        if (lane >= o) { s.x += ax; s.y += ay; s.z += az; }
    }
    if (lane == 31) s_wsum[warp] = s;
    __syncthreads();
    if (warp == 0) {
        float3 ws = s_wsum[lane];
        #pragma unroll
        for (int o = 1; o < 32; o <<= 1) {
            float ax = __shfl_up_sync(0xFFFFFFFFu, ws.x, o);
            float ay = __shfl_up_sync(0xFFFFFFFFu, ws.y, o);
            float az = __shfl_up_sync(0xFFFFFFFFu, ws.z, o);
            if (lane >= o) { ws.x += ax; ws.y += ay; ws.z += az; }
        }
        s_wsum[lane] = ws;
    }
    __syncthreads();
    float3 prefix = (warp > 0) ? s_wsum[warp - 1] : make_float3(0.f, 0.f, 0.f);
    float3 incl = make_float3(s.x + prefix.x, s.y + prefix.y, s.z + prefix.z);
    float3 excl;
    excl.x = __shfl_up_sync(0xFFFFFFFFu, incl.x, 1);
    excl.y = __shfl_up_sync(0xFFFFFFFFu, incl.y, 1);
    excl.z = __shfl_up_sync(0xFFFFFFFFu, incl.z, 1);
    if (lane == 0) excl = prefix;
    float3 p0 = s_pos0;
    g_traj[b * T + t] = make_float3(p0.x + excl.x, 0.f, p0.z + excl.z);
}

__global__ void __launch_bounds__(256) main_kernel(
    const float* __restrict__ glb_pos,
    const float4* __restrict__ glb_rot,
    const float4* __restrict__ root,
    float* __restrict__ out_pos,
    float4* __restrict__ out_rot,
    int T, int J, int total)
{
    int idx = blockIdx.x * blockDim.x + threadIdx.x;
    if (idx >= total) return;
    int tj = T * J;
    int b = idx / tj;
    int t = (idx - b * tj) / J;

    Q inv = load_inv(root, b * T + t);
    long pbase = (long)idx * 3;
    float3 p = make_float3(__ldg(glb_pos + pbase), __ldg(glb_pos + pbase + 1),
                           __ldg(glb_pos + pbase + 2));
    float3 pr = qapply(inv, p);
    float3 tr = g_traj[b * T + t];
    out_pos[pbase]     = pr.x + tr.x;
    out_pos[pbase + 1] = pr.y;
    out_pos[pbase + 2] = pr.z + tr.z;

    float4 r4 = __ldg(glb_rot + idx);
    Q r; r.w = r4.x; r.x = r4.y; r.y = r4.z; r.z = r4.w;
    Q m = qmul(inv, r);
    if (m.w < 0.f) { m.w = -m.w; m.x = -m.x; m.y = -m.y; m.z = -m.z; }
    out_rot[idx] = make_float4(m.w, m.x, m.y, m.z);
}

extern "C" void kernel_launch(void* const* d_in, const int* in_sizes, int n_in,
                              void* d_out, int out_size)
{
    const float* glb_pos = (const float*)d_in[0];   // B*T*J*3
    const float* glb_rot = (const float*)d_in[1];   // B*T*J*4
    const float* glb_vel = (const float*)d_in[2];   // B*(T-1)*J*3
    const float* root    = (const float*)d_in[3];   // B*T*4

    int J = (int)((4LL * in_sizes[0]) / (3LL * in_sizes[3]));
    int B = (in_sizes[0] - in_sizes[2]) / (3 * J);
    int T = in_sizes[3] / (4 * B);
    int total = B * T * J;

    float*  out_pos = (float*)d_out;
    float4* out_rot = (float4*)((float*)d_out + (long)total * 3);

    if (J == 32 && T == 1024 && B == 64) {
        int blocks = total / 1024;                    // 2048
        fused_one<<<blocks, 256>>>((const float4*)glb_pos,
                                   (const float4*)glb_rot,
                                   glb_vel, (const float4*)root,
                                   (float4*)out_pos, (float4*)out_rot);
    } else {
        traj_kernel<<<B, T>>>(glb_pos, glb_vel, (const float4*)root, T, J);
        int threads = 256;
        int blocks = (total + threads - 1) / threads;
        main_kernel<<<blocks, threads>>>(glb_pos, (const float4*)glb_rot,
                                         (const float4*)root,
                                         out_pos, out_rot, T, J, total);
    }
}

// round 5
// speedup vs baseline: 1.1700x; 1.1700x over previous
#include <cuda_runtime.h>

// glb_pos [B,T,J,3], glb_rot [B,T,J,4], glb_vel [B,T-1,J,3], root_rotation [B,T,1,4]
// Output: pos_out [B,T,J,3] then rot_out [B,T,J,4], float32.

#define MAX_B 64
#define MAX_T 1024

__device__ float2 g_traj2[MAX_B * MAX_T];  // fast path: (x,z) trajectory
__device__ float3 g_traj[MAX_B * MAX_T];   // fallback path scratch

struct Q { float w, x, y, z; };

__device__ __forceinline__ Q qmul(Q a, Q b) {
    Q r;
    r.w = a.w * b.w - a.x * b.x - a.y * b.y - a.z * b.z;
    r.x = a.w * b.x + a.x * b.w + a.y * b.z - a.z * b.y;
    r.y = a.w * b.y - a.x * b.z + a.y * b.w + a.z * b.x;
    r.z = a.w * b.z + a.x * b.y - a.y * b.x + a.z * b.w;
    return r;
}

__device__ __forceinline__ float3 qapply(Q q, float3 p) {
    Q pq; pq.w = 0.f; pq.x = p.x; pq.y = p.y; pq.z = p.z;
    Q t = qmul(q, pq);
    Q c; c.w = q.w; c.x = -q.x; c.y = -q.y; c.z = -q.z;
    Q r = qmul(t, c);
    return make_float3(r.x, r.y, r.z);
}

__device__ __forceinline__ Q load_inv(const float4* __restrict__ root, int idx) {
    float4 v = __ldg(root + idx);                        // (w,x,y,z) real-first
    Q q; q.w = v.x; q.x = -v.y; q.y = -v.z; q.z = -v.w;  // conjugate
    return q;
}

// ===========================================================================
// FAST PATH (B==64, T==1024, J==32): two plain launches.
//   Kernel 1: blocks [0,64)  -> per-batch trajectory scan into g_traj2;
//             blocks [64,..) -> rot path, warp-contiguous float4 accesses.
//             Scan cost hides under the rot DRAM traffic (independent work).
//   Kernel 2: pos path, 1 element/thread, scalar 3-float IO (R1's proven
//             pattern), shift-only indexing. Stream order makes g_traj2 safe.
// ===========================================================================

__global__ void __launch_bounds__(256) k_rot_traj(
    const float* __restrict__ glb_pos,
    const float4* __restrict__ glb_rot4,
    const float* __restrict__ glb_vel,
    const float4* __restrict__ root,
    float4* __restrict__ out_rot4)
{
    const int T = 1024, J = 32;
    const int tid = threadIdx.x;
    const int blk = blockIdx.x;

    if (blk < 64) {
        // ---------------- trajectory scan for batch b ----------------------
        const int b = blk;
        const int lane = tid & 31, warp = tid >> 5;     // 8 warps
        __shared__ float3 s_ws[8];
        __shared__ float3 s_pos0;

        float3 vr[4];
        float3 acc = make_float3(0.f, 0.f, 0.f);
        #pragma unroll
        for (int k = 0; k < 4; ++k) {
            int t = tid * 4 + k;
            Q inv = load_inv(root, b * T + t);
            float3 v = make_float3(0.f, 0.f, 0.f);
            if (t < T - 1) {
                const float* vp = glb_vel + ((b * (T - 1) + t) * J) * 3;  // joint 0
                v = qapply(inv, make_float3(__ldg(vp), __ldg(vp + 1), __ldg(vp + 2)));
            }
            if (t == 0) {
                const float* pp = glb_pos + (long)b * T * J * 3;
                s_pos0 = qapply(inv, make_float3(__ldg(pp), __ldg(pp + 1), __ldg(pp + 2)));
            }
            acc.x += v.x; acc.y += v.y; acc.z += v.z;
            vr[k] = acc;
        }

        float3 s = acc;
        #pragma unroll
        for (int o = 1; o < 32; o <<= 1) {
            float ax = __shfl_up_sync(0xFFFFFFFFu, s.x, o);
            float ay = __shfl_up_sync(0xFFFFFFFFu, s.y, o);
            float az = __shfl_up_sync(0xFFFFFFFFu, s.z, o);
            if (lane >= o) { s.x += ax; s.y += ay; s.z += az; }
        }
        if (lane == 31) s_ws[warp] = s;
        __syncthreads();
        if (warp == 0 && lane < 8) {
            float3 ws = s_ws[lane];
            #pragma unroll
            for (int o = 1; o < 8; o <<= 1) {
                float ax = __shfl_up_sync(0x000000FFu, ws.x, o);
                float ay = __shfl_up_sync(0x000000FFu, ws.y, o);
                float az = __shfl_up_sync(0x000000FFu, ws.z, o);
                if (lane >= o) { ws.x += ax; ws.y += ay; ws.z += az; }
            }
            s_ws[lane] = ws;
        }
        __syncthreads();

        float3 wpre = (warp > 0) ? s_ws[warp - 1] : make_float3(0.f, 0.f, 0.f);
        float3 incl = make_float3(s.x + wpre.x, s.y + wpre.y, s.z + wpre.z);
        float3 excl;
        excl.x = __shfl_up_sync(0xFFFFFFFFu, incl.x, 1);
        excl.y = __shfl_up_sync(0xFFFFFFFFu, incl.y, 1);
        excl.z = __shfl_up_sync(0xFFFFFFFFu, incl.z, 1);
        if (lane == 0) excl = wpre;

        float3 p0 = s_pos0;
        #pragma unroll
        for (int k = 0; k < 4; ++k) {
            float ex = excl.x, ez = excl.z;
            if (k > 0) { ex += vr[k - 1].x; ez += vr[k - 1].z; }
            g_traj2[b * T + tid * 4 + k] = make_float2(p0.x + ex, p0.z + ez);
        }
    } else {
        // ---------------- rot path: warp-contiguous float4 -----------------
        const int base = (blk - 64) * 1024;            // 1024 quats per block
        #pragma unroll
        for (int k = 0; k < 4; ++k) {
            int idx = base + k * 256 + tid;            // consecutive per lane
            Q inv = load_inv(root, idx >> 5);          // warp-uniform broadcast
            float4 r4 = __ldg(glb_rot4 + idx);
            Q r; r.w = r4.x; r.x = r4.y; r.y = r4.z; r.z = r4.w;
            Q m = qmul(inv, r);
            if (m.w < 0.f) { m.w = -m.w; m.x = -m.x; m.y = -m.y; m.z = -m.z; }
            out_rot4[idx] = make_float4(m.w, m.x, m.y, m.z);
        }
    }
}

__global__ void __launch_bounds__(256) k_pos(
    const float* __restrict__ glb_pos,
    const float4* __restrict__ root,
    float* __restrict__ out_pos)
{
    const int idx = blockIdx.x * 256 + threadIdx.x;    // element (b,t,j)
    const int bt = idx >> 5;                           // J==32

    Q inv = load_inv(root, bt);                        // warp-uniform
    float2 tr = g_traj2[bt];                           // warp-uniform

    const int base = idx * 3;
    float3 p = make_float3(__ldg(glb_pos + base),
                           __ldg(glb_pos + base + 1),
                           __ldg(glb_pos + base + 2));
    float3 pr = qapply(inv, p);
    out_pos[base]     = pr.x + tr.x;
    out_pos[base + 1] = pr.y;                          // xz mask: y untouched
    out_pos[base + 2] = pr.z + tr.y;
}

// ===========================================================================
// Fallback (generic dims): R1's proven two-kernel path.
// ===========================================================================
__global__ void __launch_bounds__(1024) traj_kernel(
    const float* __restrict__ glb_pos,
    const float* __restrict__ glb_vel,
    const float4* __restrict__ root,
    int T, int J)
{
    const int b = blockIdx.x;
    const int t = threadIdx.x;
    const int lane = t & 31, warp = t >> 5;
    __shared__ float3 s_wsum[32];
    __shared__ float3 s_pos0;
    if (t >= T) return;

    Q inv = load_inv(root, b * T + t);
    float3 v = make_float3(0.f, 0.f, 0.f);
    if (t < T - 1) {
        const float* vp = glb_vel + ((long)(b * (T - 1) + t) * J) * 3;
        v = qapply(inv, make_float3(__ldg(vp), __ldg(vp + 1), __ldg(vp + 2)));
    }
    if (t == 0) {
        const float* pp = glb_pos + (long)b * T * J * 3;
        s_pos0 = qapply(inv, make_float3(__ldg(pp), __ldg(pp + 1), __ldg(pp + 2)));
    }
    float3 s = v;
    #pragma unroll
    for (int o = 1; o < 32; o <<= 1) {
        float ax = __shfl_up_sync(0xFFFFFFFFu, s.x, o);
        float ay = __shfl_up_sync(0xFFFFFFFFu, s.y, o);
        float az = __shfl_up_sync(0xFFFFFFFFu, s.z, o);
        if (lane >= o) { s.x += ax; s.y += ay; s.z += az; }
    }
    if (lane == 31) s_wsum[warp] = s;
    __syncthreads();
    if (warp == 0) {
        float3 ws = s_wsum[lane];
        #pragma unroll
        for (int o = 1; o < 32; o <<= 1) {
            float ax = __shfl_up_sync(0xFFFFFFFFu, ws.x, o);
            float ay = __shfl_up_sync(0xFFFFFFFFu, ws.y, o);
            float az = __shfl_up_sync(0xFFFFFFFFu, ws.z, o);
            if (lane >= o) { ws.x += ax; ws.y += ay; ws.z += az; }
        }
        s_wsum[lane] = ws;
    }
    __syncthreads();
    float3 prefix = (warp > 0) ? s_wsum[warp - 1] : make_float3(0.f, 0.f, 0.f);
    float3 incl = make_float3(s.x + prefix.x, s.y + prefix.y, s.z + prefix.z);
    float3 excl;
    excl.x = __shfl_up_sync(0xFFFFFFFFu, incl.x, 1);
    excl.y = __shfl_up_sync(0xFFFFFFFFu, incl.y, 1);
    excl.z = __shfl_up_sync(0xFFFFFFFFu, incl.z, 1);
    if (lane == 0) excl = prefix;
    float3 p0 = s_pos0;
    g_traj[b * T + t] = make_float3(p0.x + excl.x, 0.f, p0.z + excl.z);
}

__global__ void __launch_bounds__(256) main_kernel(
    const float* __restrict__ glb_pos,
    const float4* __restrict__ glb_rot,
    const float4* __restrict__ root,
    float* __restrict__ out_pos,
    float4* __restrict__ out_rot,
    int T, int J, int total)
{
    int idx = blockIdx.x * blockDim.x + threadIdx.x;
    if (idx >= total) return;
    int tj = T * J;
    int b = idx / tj;
    int t = (idx - b * tj) / J;

    Q inv = load_inv(root, b * T + t);
    long pbase = (long)idx * 3;
    float3 p = make_float3(__ldg(glb_pos + pbase), __ldg(glb_pos + pbase + 1),
                           __ldg(glb_pos + pbase + 2));
    float3 pr = qapply(inv, p);
    float3 tr = g_traj[b * T + t];
    out_pos[pbase]     = pr.x + tr.x;
    out_pos[pbase + 1] = pr.y;
    out_pos[pbase + 2] = pr.z + tr.z;

    float4 r4 = __ldg(glb_rot + idx);
    Q r; r.w = r4.x; r.x = r4.y; r.y = r4.z; r.z = r4.w;
    Q m = qmul(inv, r);
    if (m.w < 0.f) { m.w = -m.w; m.x = -m.x; m.y = -m.y; m.z = -m.z; }
    out_rot[idx] = make_float4(m.w, m.x, m.y, m.z);
}

extern "C" void kernel_launch(void* const* d_in, const int* in_sizes, int n_in,
                              void* d_out, int out_size)
{
    const float* glb_pos = (const float*)d_in[0];   // B*T*J*3
    const float* glb_rot = (const float*)d_in[1];   // B*T*J*4
    const float* glb_vel = (const float*)d_in[2];   // B*(T-1)*J*3
    const float* root    = (const float*)d_in[3];   // B*T*4

    int J = (int)((4LL * in_sizes[0]) / (3LL * in_sizes[3]));
    int B = (in_sizes[0] - in_sizes[2]) / (3 * J);
    int T = in_sizes[3] / (4 * B);
    int total = B * T * J;

    float*  out_pos = (float*)d_out;
    float4* out_rot = (float4*)((float*)d_out + (long)total * 3);

    if (J == 32 && T == 1024 && B == 64) {
        int rot_blocks = total / 1024;                // 2048
        k_rot_traj<<<64 + rot_blocks, 256>>>(glb_pos, (const float4*)glb_rot,
                                             glb_vel, (const float4*)root,
                                             (float4*)out_rot);
        k_pos<<<total / 256, 256>>>(glb_pos, (const float4*)root, out_pos);
    } else {
        traj_kernel<<<B, T>>>(glb_pos, glb_vel, (const float4*)root, T, J);
        int threads = 256;
        int blocks = (total + threads - 1) / threads;
        main_kernel<<<blocks, threads>>>(glb_pos, (const float4*)glb_rot,
                                         (const float4*)root,
                                         out_pos, out_rot, T, J, total);
    }
}